// round 3
// baseline (speedup 1.0000x reference)
#include <cuda_runtime.h>
#include <math.h>

#define INV_SCALE 0.35355339059327373f
#define C_CH 28

// Scratch volumes (alloc-free rule: __device__ globals)
__device__ float g_vol0[C_CH * 32 * 32 * 32];                 // channel-first
__device__ float g_vol1[C_CH * 64 * 64 * 64];                 // channel-first
__device__ float g_vol2[128 * 128 * 128 * C_CH];              // channel-LAST [z][y][x][c]

// 8-point Haar synthesis butterfly. Inputs c_{uvw}; outputs o[p*4+q*2+r],
// o_{pqr} = INV_SCALE * sum_{uvw} (-1)^{up+vq+wr} c_{uvw}
__device__ __forceinline__ void haar8(float c000, float c001, float c010, float c011,
                                      float c100, float c101, float c110, float c111,
                                      float o[8]) {
    // w -> r
    float r0_00 = c000 + c001, r1_00 = c000 - c001;
    float r0_01 = c010 + c011, r1_01 = c010 - c011;
    float r0_10 = c100 + c101, r1_10 = c100 - c101;
    float r0_11 = c110 + c111, r1_11 = c110 - c111;
    // v -> q
    float q0r0_0 = r0_00 + r0_01, q1r0_0 = r0_00 - r0_01;
    float q0r1_0 = r1_00 + r1_01, q1r1_0 = r1_00 - r1_01;
    float q0r0_1 = r0_10 + r0_11, q1r0_1 = r0_10 - r0_11;
    float q0r1_1 = r1_10 + r1_11, q1r1_1 = r1_10 - r1_11;
    // u -> p
    o[0] = (q0r0_0 + q0r0_1) * INV_SCALE;  // p0 q0 r0
    o[1] = (q0r1_0 + q0r1_1) * INV_SCALE;  // p0 q0 r1
    o[2] = (q1r0_0 + q1r0_1) * INV_SCALE;  // p0 q1 r0
    o[3] = (q1r1_0 + q1r1_1) * INV_SCALE;  // p0 q1 r1
    o[4] = (q0r0_0 - q0r0_1) * INV_SCALE;  // p1 q0 r0
    o[5] = (q0r1_0 - q0r1_1) * INV_SCALE;  // p1 q0 r1
    o[6] = (q1r0_0 - q1r0_1) * INV_SCALE;  // p1 q1 r0
    o[7] = (q1r1_0 - q1r1_1) * INV_SCALE;  // p1 q1 r1
}

// Generic channel-first -> channel-first idwt. One thread per input cell.
template <int D>
__device__ __forceinline__ void idwt_cf_body(const float* __restrict__ approx,
                                             const float* __restrict__ det,
                                             float* __restrict__ out) {
    const int D3 = D * D * D;
    int tid = blockIdx.x * blockDim.x + threadIdx.x;
    if (tid >= C_CH * D3) return;
    int k = tid % D;
    int j = (tid / D) % D;
    int i = (tid / (D * D)) % D;
    int c = tid / D3;

    float a = approx[tid];
    float d0 = det[0 * C_CH * D3 + tid];
    float d1 = det[1 * C_CH * D3 + tid];
    float d2 = det[2 * C_CH * D3 + tid];
    float d3 = det[3 * C_CH * D3 + tid];
    float d4 = det[4 * C_CH * D3 + tid];
    float d5 = det[5 * C_CH * D3 + tid];
    float d6 = det[6 * C_CH * D3 + tid];

    float o[8];
    haar8(a, d0, d1, d2, d3, d4, d5, d6, o);

    const int D2 = 2 * D;
    int base = ((c * D2 + 2 * i) * D2 + 2 * j) * D2 + 2 * k;
    out[base]               = o[0];
    out[base + 1]           = o[1];
    out[base + D2]          = o[2];
    out[base + D2 + 1]      = o[3];
    out[base + D2 * D2]         = o[4];
    out[base + D2 * D2 + 1]     = o[5];
    out[base + D2 * D2 + D2]    = o[6];
    out[base + D2 * D2 + D2 + 1]= o[7];
}

__global__ void idwt_l0(const float* __restrict__ approx, const float* __restrict__ det) {
    idwt_cf_body<16>(approx, det, g_vol0);
}
__global__ void idwt_l1(const float* __restrict__ det) {
    idwt_cf_body<32>(g_vol0, det, g_vol1);
}

// Level 2: channel-first (g_vol1 + details_2, D=64) -> channel-LAST g_vol2 (128^3 x 28).
// Block = one (i, j, k-half) input row, all 28 channels.
// Phase A: coalesced stage of 8 subbands x 28 ch x 32 k into smem (stride-33 pad).
// Phase B: lane = channel; each lane emits 8 outputs per input cell; a warp's 28
//          active lanes write 112B-contiguous chunks in the channel-last volume.
__global__ void __launch_bounds__(256) idwt_l2(const float* __restrict__ det) {
    __shared__ float sm[8 * C_CH * 33];   // [s*28+c][33] pad -> conflict-free stride

    const int j  = blockIdx.x;
    const int i  = blockIdx.y;
    const int k0 = blockIdx.z * 32;
    const int tid = threadIdx.x;

    const int rowbase = i * 64 * 64 + j * 64 + k0;  // offset within one channel plane (64^3)

    // Phase A: 8*28 rows of 32 floats
    for (int r = tid; r < 8 * C_CH * 32; r += 256) {
        int kk  = r & 31;
        int row = r >> 5;             // s*28 + c
        int s   = row / C_CH;
        int c   = row - s * C_CH;
        const float* src = (s == 0)
            ? (g_vol1 + c * 262144 + rowbase)
            : (det + ((s - 1) * C_CH + c) * 262144 + rowbase);
        sm[row * 33 + kk] = src[kk];
    }
    __syncthreads();

    const int lane = tid & 31;
    const int w    = tid >> 5;        // warp id, 8 warps -> 4 k each
    if (lane < C_CH) {
        const int c = lane;
#pragma unroll
        for (int it = 0; it < 4; it++) {
            int kk = w * 4 + it;
            float c000 = sm[(0 * C_CH + c) * 33 + kk];
            float c001 = sm[(1 * C_CH + c) * 33 + kk];
            float c010 = sm[(2 * C_CH + c) * 33 + kk];
            float c011 = sm[(3 * C_CH + c) * 33 + kk];
            float c100 = sm[(4 * C_CH + c) * 33 + kk];
            float c101 = sm[(5 * C_CH + c) * 33 + kk];
            float c110 = sm[(6 * C_CH + c) * 33 + kk];
            float c111 = sm[(7 * C_CH + c) * 33 + kk];
            float o[8];
            haar8(c000, c001, c010, c011, c100, c101, c110, c111, o);

            int X0 = 2 * (k0 + kk);
            // base voxel (2i, 2j, X0), channel c, layout [z][y][x][c]
            int base = (((2 * i) * 128 + (2 * j)) * 128 + X0) * C_CH + c;
            const int SP = 128 * 128 * C_CH;   // z (p) stride
            const int SQ = 128 * C_CH;         // y (q) stride
            const int SR = C_CH;               // x (r) stride
            g_vol2[base]                = o[0];
            g_vol2[base + SR]           = o[1];
            g_vol2[base + SQ]           = o[2];
            g_vol2[base + SQ + SR]      = o[3];
            g_vol2[base + SP]           = o[4];
            g_vol2[base + SP + SR]      = o[5];
            g_vol2[base + SP + SQ]      = o[6];
            g_vol2[base + SP + SQ + SR] = o[7];
        }
    }
}

// Trilinear query over channel-last volume. One thread per point, acc[28] in regs.
__global__ void __launch_bounds__(128) query_k(const float* __restrict__ xyz,
                                               float* __restrict__ out, int N) {
    int n = blockIdx.x * blockDim.x + threadIdx.x;
    if (n >= N) return;

    float x = xyz[3 * n + 0];
    float y = xyz[3 * n + 1];
    float z = xyz[3 * n + 2];

    const float invb = 1.0f / 1.5f;
    const float half127 = 0.5f * 127.0f;
    float px = (x * invb + 1.0f) * half127;
    float py = (y * invb + 1.0f) * half127;
    float pz = (z * invb + 1.0f) * half127;

    float fpx = floorf(px), fpy = floorf(py), fpz = floorf(pz);
    int ix0 = (int)fpx, iy0 = (int)fpy, iz0 = (int)fpz;
    float fx = px - fpx, fy = py - fpy, fz = pz - fpz;

    const float* __restrict__ vp = (const float*)g_vol2;

    float acc[C_CH];
#pragma unroll
    for (int c = 0; c < C_CH; c++) acc[c] = 0.0f;

#pragma unroll
    for (int dz = 0; dz < 2; dz++) {
        int iz = iz0 + dz;
        float wz = dz ? fz : (1.0f - fz);
        bool vz = (iz >= 0) & (iz < 128);
        int izc = min(max(iz, 0), 127);
#pragma unroll
        for (int dy = 0; dy < 2; dy++) {
            int iy = iy0 + dy;
            float wy = dy ? fy : (1.0f - fy);
            bool vy = (iy >= 0) & (iy < 128);
            int iyc = min(max(iy, 0), 127);
#pragma unroll
            for (int dx = 0; dx < 2; dx++) {
                int ix = ix0 + dx;
                float wx = dx ? fx : (1.0f - fx);
                bool vx = (ix >= 0) & (ix < 128);
                int ixc = min(max(ix, 0), 127);

                float wgt = wx * wy * wz;
                wgt = (vx & vy & vz) ? wgt : 0.0f;

                const float4* p =
                    (const float4*)(vp + ((izc * 128 + iyc) * 128 + ixc) * C_CH);
#pragma unroll
                for (int t = 0; t < 7; t++) {
                    float4 v = p[t];
                    acc[4 * t + 0] = fmaf(wgt, v.x, acc[4 * t + 0]);
                    acc[4 * t + 1] = fmaf(wgt, v.y, acc[4 * t + 1]);
                    acc[4 * t + 2] = fmaf(wgt, v.z, acc[4 * t + 2]);
                    acc[4 * t + 3] = fmaf(wgt, v.w, acc[4 * t + 3]);
                }
            }
        }
    }

    float4* po = (float4*)(out + (long)n * C_CH);
#pragma unroll
    for (int t = 0; t < 7; t++) {
        po[t] = make_float4(acc[4 * t + 0], acc[4 * t + 1], acc[4 * t + 2], acc[4 * t + 3]);
    }
}

extern "C" void kernel_launch(void* const* d_in, const int* in_sizes, int n_in,
                              void* d_out, int out_size) {
    const float* approx    = (const float*)d_in[0];   // (28,16,16,16)
    const float* details_0 = (const float*)d_in[1];   // (7,28,16,16,16)
    const float* details_1 = (const float*)d_in[2];   // (7,28,32,32,32)
    const float* details_2 = (const float*)d_in[3];   // (7,28,64,64,64)
    const float* xyz       = (const float*)d_in[4];   // (N,3)
    float* out = (float*)d_out;

    int N = in_sizes[4] / 3;

    // Level 0: 28*16^3 cells
    idwt_l0<<<(C_CH * 4096 + 255) / 256, 256>>>(approx, details_0);
    // Level 1: 28*32^3 cells
    idwt_l1<<<(C_CH * 32768 + 255) / 256, 256>>>(details_1);
    // Level 2: (j, i, k-half) blocks
    dim3 g2(64, 64, 2);
    idwt_l2<<<g2, 256>>>(details_2);
    // Query
    query_k<<<(N + 127) / 128, 128>>>(xyz, out, N);
}

// round 4
// speedup vs baseline: 2.4260x; 2.4260x over previous
#include <cuda_runtime.h>
#include <cuda_fp16.h>
#include <math.h>

#define INV_SCALE 0.35355339059327373f
#define C_CH 28

// Scratch volumes (alloc-free rule: __device__ globals)
__device__ float  g_vol0[C_CH * 32 * 32 * 32];                 // channel-first fp32
__device__ float  g_vol1[C_CH * 64 * 64 * 64];                 // channel-first fp32
__device__ __half g_vol2[128 * 128 * 128 * C_CH];              // channel-LAST [z][y][x][c], fp16

// 8-point Haar synthesis butterfly. Inputs c_{uvw}; outputs o[p*4+q*2+r],
// o_{pqr} = INV_SCALE * sum_{uvw} (-1)^{up+vq+wr} c_{uvw}
__device__ __forceinline__ void haar8(float c000, float c001, float c010, float c011,
                                      float c100, float c101, float c110, float c111,
                                      float o[8]) {
    float r0_00 = c000 + c001, r1_00 = c000 - c001;
    float r0_01 = c010 + c011, r1_01 = c010 - c011;
    float r0_10 = c100 + c101, r1_10 = c100 - c101;
    float r0_11 = c110 + c111, r1_11 = c110 - c111;
    float q0r0_0 = r0_00 + r0_01, q1r0_0 = r0_00 - r0_01;
    float q0r1_0 = r1_00 + r1_01, q1r1_0 = r1_00 - r1_01;
    float q0r0_1 = r0_10 + r0_11, q1r0_1 = r0_10 - r0_11;
    float q0r1_1 = r1_10 + r1_11, q1r1_1 = r1_10 - r1_11;
    o[0] = (q0r0_0 + q0r0_1) * INV_SCALE;
    o[1] = (q0r1_0 + q0r1_1) * INV_SCALE;
    o[2] = (q1r0_0 + q1r0_1) * INV_SCALE;
    o[3] = (q1r1_0 + q1r1_1) * INV_SCALE;
    o[4] = (q0r0_0 - q0r0_1) * INV_SCALE;
    o[5] = (q0r1_0 - q0r1_1) * INV_SCALE;
    o[6] = (q1r0_0 - q1r0_1) * INV_SCALE;
    o[7] = (q1r1_0 - q1r1_1) * INV_SCALE;
}

// Channel-first -> channel-first idwt (levels 0, 1). One thread per input cell.
template <int D>
__device__ __forceinline__ void idwt_cf_body(const float* __restrict__ approx,
                                             const float* __restrict__ det,
                                             float* __restrict__ out) {
    const int D3 = D * D * D;
    int tid = blockIdx.x * blockDim.x + threadIdx.x;
    if (tid >= C_CH * D3) return;
    int k = tid % D;
    int j = (tid / D) % D;
    int i = (tid / (D * D)) % D;
    int c = tid / D3;

    float a  = approx[tid];
    float d0 = det[0 * C_CH * D3 + tid];
    float d1 = det[1 * C_CH * D3 + tid];
    float d2 = det[2 * C_CH * D3 + tid];
    float d3 = det[3 * C_CH * D3 + tid];
    float d4 = det[4 * C_CH * D3 + tid];
    float d5 = det[5 * C_CH * D3 + tid];
    float d6 = det[6 * C_CH * D3 + tid];

    float o[8];
    haar8(a, d0, d1, d2, d3, d4, d5, d6, o);

    const int D2 = 2 * D;
    int base = ((c * D2 + 2 * i) * D2 + 2 * j) * D2 + 2 * k;
    out[base]                    = o[0];
    out[base + 1]                = o[1];
    out[base + D2]               = o[2];
    out[base + D2 + 1]           = o[3];
    out[base + D2 * D2]          = o[4];
    out[base + D2 * D2 + 1]      = o[5];
    out[base + D2 * D2 + D2]     = o[6];
    out[base + D2 * D2 + D2 + 1] = o[7];
}

__global__ void idwt_l0(const float* __restrict__ approx, const float* __restrict__ det) {
    idwt_cf_body<16>(approx, det, g_vol0);
}
__global__ void idwt_l1(const float* __restrict__ det) {
    idwt_cf_body<32>(g_vol0, det, g_vol1);
}

// Level 2: channel-first fp32 (g_vol1 + details_2, D=64) -> channel-LAST fp16 g_vol2.
// Block = one (i, j, 32-wide k range) input row, all 28 channels.
// Phase A: coalesced stage of 8 subbands x 28 ch x 32 k into smem (stride-33 pad).
// Phase B: thread = channel PAIR (2p, 2p+1); lanes 0-13 -> one k sample, lanes
//          16-29 -> another; outputs packed as half2 -> 4B stores, 56B contiguous
//          per 14-lane group in the channel-last volume.
__global__ void __launch_bounds__(256) idwt_l2(const float* __restrict__ det) {
    __shared__ float sm[8 * C_CH * 33];

    const int j  = blockIdx.x;
    const int i  = blockIdx.y;
    const int k0 = blockIdx.z * 32;
    const int tid = threadIdx.x;

    const int rowbase = i * 64 * 64 + j * 64 + k0;  // within one 64^3 channel plane

    for (int r = tid; r < 8 * C_CH * 32; r += 256) {
        int kk  = r & 31;
        int row = r >> 5;             // s*28 + c
        int s   = row / C_CH;
        int c   = row - s * C_CH;
        const float* src = (s == 0)
            ? (g_vol1 + c * 262144 + rowbase)
            : (det + ((s - 1) * C_CH + c) * 262144 + rowbase);
        sm[row * 33 + kk] = src[kk];
    }
    __syncthreads();

    const int lane = tid & 31;
    const int w    = tid >> 5;          // 8 warps
    const int grp  = lane >> 4;         // 0 or 1 (half-warp)
    const int p    = lane & 15;         // channel-pair index, active if < 14
    if (p < 14) {
        const int c0 = 2 * p;
#pragma unroll
        for (int it = 0; it < 2; it++) {
            int kk = it * 16 + w * 2 + grp;   // 0..31
            float oA[8], oB[8];
            haar8(sm[(0 * C_CH + c0) * 33 + kk], sm[(1 * C_CH + c0) * 33 + kk],
                  sm[(2 * C_CH + c0) * 33 + kk], sm[(3 * C_CH + c0) * 33 + kk],
                  sm[(4 * C_CH + c0) * 33 + kk], sm[(5 * C_CH + c0) * 33 + kk],
                  sm[(6 * C_CH + c0) * 33 + kk], sm[(7 * C_CH + c0) * 33 + kk], oA);
            haar8(sm[(0 * C_CH + c0 + 1) * 33 + kk], sm[(1 * C_CH + c0 + 1) * 33 + kk],
                  sm[(2 * C_CH + c0 + 1) * 33 + kk], sm[(3 * C_CH + c0 + 1) * 33 + kk],
                  sm[(4 * C_CH + c0 + 1) * 33 + kk], sm[(5 * C_CH + c0 + 1) * 33 + kk],
                  sm[(6 * C_CH + c0 + 1) * 33 + kk], sm[(7 * C_CH + c0 + 1) * 33 + kk], oB);

            int X0 = 2 * (k0 + kk);
            // base voxel (2i, 2j, X0), channels (c0, c0+1); element index is even
            int base = (((2 * i) * 128 + (2 * j)) * 128 + X0) * C_CH + c0;
            __half2* v = (__half2*)(g_vol2 + base);
            const int SP = (128 * 128 * C_CH) / 2;   // z stride in half2
            const int SQ = (128 * C_CH) / 2;         // y stride in half2
            const int SR = C_CH / 2;                 // x stride in half2
            v[0]            = __floats2half2_rn(oA[0], oB[0]);
            v[SR]           = __floats2half2_rn(oA[1], oB[1]);
            v[SQ]           = __floats2half2_rn(oA[2], oB[2]);
            v[SQ + SR]      = __floats2half2_rn(oA[3], oB[3]);
            v[SP]           = __floats2half2_rn(oA[4], oB[4]);
            v[SP + SR]      = __floats2half2_rn(oA[5], oB[5]);
            v[SP + SQ]      = __floats2half2_rn(oA[6], oB[6]);
            v[SP + SQ + SR] = __floats2half2_rn(oA[7], oB[7]);
        }
    }
}

// Trilinear query over channel-last fp16 volume. One thread per point, fp32 acc.
__global__ void __launch_bounds__(128) query_k(const float* __restrict__ xyz,
                                               float* __restrict__ out, int N) {
    int n = blockIdx.x * blockDim.x + threadIdx.x;
    if (n >= N) return;

    float x = xyz[3 * n + 0];
    float y = xyz[3 * n + 1];
    float z = xyz[3 * n + 2];

    const float invb = 1.0f / 1.5f;
    const float half127 = 0.5f * 127.0f;
    float px = (x * invb + 1.0f) * half127;
    float py = (y * invb + 1.0f) * half127;
    float pz = (z * invb + 1.0f) * half127;

    float fpx = floorf(px), fpy = floorf(py), fpz = floorf(pz);
    int ix0 = (int)fpx, iy0 = (int)fpy, iz0 = (int)fpz;
    float fx = px - fpx, fy = py - fpy, fz = pz - fpz;

    const __half* __restrict__ vp = (const __half*)g_vol2;

    float acc[C_CH];
#pragma unroll
    for (int c = 0; c < C_CH; c++) acc[c] = 0.0f;

#pragma unroll
    for (int dz = 0; dz < 2; dz++) {
        int iz = iz0 + dz;
        float wz = dz ? fz : (1.0f - fz);
        bool vz = (iz >= 0) & (iz < 128);
        int izc = min(max(iz, 0), 127);
#pragma unroll
        for (int dy = 0; dy < 2; dy++) {
            int iy = iy0 + dy;
            float wy = dy ? fy : (1.0f - fy);
            bool vy = (iy >= 0) & (iy < 128);
            int iyc = min(max(iy, 0), 127);
#pragma unroll
            for (int dx = 0; dx < 2; dx++) {
                int ix = ix0 + dx;
                float wx = dx ? fx : (1.0f - fx);
                bool vx = (ix >= 0) & (ix < 128);
                int ixc = min(max(ix, 0), 127);

                float wgt = wx * wy * wz;
                wgt = (vx & vy & vz) ? wgt : 0.0f;

                // 28 halfs = 56 B, 8-byte aligned (idx*56 % 8 == 0)
                const uint2* p = (const uint2*)(vp + ((izc * 128 + iyc) * 128 + ixc) * C_CH);
#pragma unroll
                for (int t = 0; t < 7; t++) {
                    uint2 v = p[t];
                    float2 f0 = __half22float2(*(const __half2*)&v.x);
                    float2 f1 = __half22float2(*(const __half2*)&v.y);
                    acc[4 * t + 0] = fmaf(wgt, f0.x, acc[4 * t + 0]);
                    acc[4 * t + 1] = fmaf(wgt, f0.y, acc[4 * t + 1]);
                    acc[4 * t + 2] = fmaf(wgt, f1.x, acc[4 * t + 2]);
                    acc[4 * t + 3] = fmaf(wgt, f1.y, acc[4 * t + 3]);
                }
            }
        }
    }

    float4* po = (float4*)(out + (long)n * C_CH);
#pragma unroll
    for (int t = 0; t < 7; t++) {
        po[t] = make_float4(acc[4 * t + 0], acc[4 * t + 1], acc[4 * t + 2], acc[4 * t + 3]);
    }
}

extern "C" void kernel_launch(void* const* d_in, const int* in_sizes, int n_in,
                              void* d_out, int out_size) {
    const float* approx    = (const float*)d_in[0];   // (28,16,16,16)
    const float* details_0 = (const float*)d_in[1];   // (7,28,16,16,16)
    const float* details_1 = (const float*)d_in[2];   // (7,28,32,32,32)
    const float* details_2 = (const float*)d_in[3];   // (7,28,64,64,64)
    const float* xyz       = (const float*)d_in[4];   // (N,3)
    float* out = (float*)d_out;

    int N = in_sizes[4] / 3;

    idwt_l0<<<(C_CH * 4096 + 255) / 256, 256>>>(approx, details_0);
    idwt_l1<<<(C_CH * 32768 + 255) / 256, 256>>>(details_1);
    dim3 g2(64, 64, 2);
    idwt_l2<<<g2, 256>>>(details_2);
    query_k<<<(N + 127) / 128, 128>>>(xyz, out, N);
}

// round 8
// speedup vs baseline: 2.7662x; 1.1402x over previous
#include <cuda_runtime.h>
#include <cuda_fp16.h>
#include <math.h>

#define INV_SCALE 0.35355339059327373f
#define C_CH 28
#define C_PAD 32   // padded channel stride (64 B) for aligned uint4 gathers

// Scratch volumes (alloc-free rule: __device__ globals)
__device__ float  g_vol0[C_CH * 32 * 32 * 32];                 // channel-first fp32
__device__ float  g_vol1[C_CH * 64 * 64 * 64];                 // channel-first fp32
__device__ __half g_vol2[128 * 128 * 128 * C_PAD];             // channel-LAST [z][y][x][c_pad], fp16

// 8-point Haar synthesis butterfly. Inputs c_{uvw}; outputs o[p*4+q*2+r],
// o_{pqr} = INV_SCALE * sum_{uvw} (-1)^{up+vq+wr} c_{uvw}
__device__ __forceinline__ void haar8(float c000, float c001, float c010, float c011,
                                      float c100, float c101, float c110, float c111,
                                      float o[8]) {
    float r0_00 = c000 + c001, r1_00 = c000 - c001;
    float r0_01 = c010 + c011, r1_01 = c010 - c011;
    float r0_10 = c100 + c101, r1_10 = c100 - c101;
    float r0_11 = c110 + c111, r1_11 = c110 - c111;
    float q0r0_0 = r0_00 + r0_01, q1r0_0 = r0_00 - r0_01;
    float q0r1_0 = r1_00 + r1_01, q1r1_0 = r1_00 - r1_01;
    float q0r0_1 = r0_10 + r0_11, q1r0_1 = r0_10 - r0_11;
    float q0r1_1 = r1_10 + r1_11, q1r1_1 = r1_10 - r1_11;
    o[0] = (q0r0_0 + q0r0_1) * INV_SCALE;
    o[1] = (q0r1_0 + q0r1_1) * INV_SCALE;
    o[2] = (q1r0_0 + q1r0_1) * INV_SCALE;
    o[3] = (q1r1_0 + q1r1_1) * INV_SCALE;
    o[4] = (q0r0_0 - q0r0_1) * INV_SCALE;
    o[5] = (q0r1_0 - q0r1_1) * INV_SCALE;
    o[6] = (q1r0_0 - q1r0_1) * INV_SCALE;
    o[7] = (q1r1_0 - q1r1_1) * INV_SCALE;
}

// Channel-first -> channel-first idwt (levels 0, 1). One thread per input cell.
template <int D>
__device__ __forceinline__ void idwt_cf_body(const float* __restrict__ approx,
                                             const float* __restrict__ det,
                                             float* __restrict__ out) {
    const int D3 = D * D * D;
    int tid = blockIdx.x * blockDim.x + threadIdx.x;
    if (tid >= C_CH * D3) return;
    int k = tid % D;
    int j = (tid / D) % D;
    int i = (tid / (D * D)) % D;
    int c = tid / D3;

    float a  = approx[tid];
    float d0 = det[0 * C_CH * D3 + tid];
    float d1 = det[1 * C_CH * D3 + tid];
    float d2 = det[2 * C_CH * D3 + tid];
    float d3 = det[3 * C_CH * D3 + tid];
    float d4 = det[4 * C_CH * D3 + tid];
    float d5 = det[5 * C_CH * D3 + tid];
    float d6 = det[6 * C_CH * D3 + tid];

    float o[8];
    haar8(a, d0, d1, d2, d3, d4, d5, d6, o);

    const int D2 = 2 * D;
    int base = ((c * D2 + 2 * i) * D2 + 2 * j) * D2 + 2 * k;
    out[base]                    = o[0];
    out[base + 1]                = o[1];
    out[base + D2]               = o[2];
    out[base + D2 + 1]           = o[3];
    out[base + D2 * D2]          = o[4];
    out[base + D2 * D2 + 1]      = o[5];
    out[base + D2 * D2 + D2]     = o[6];
    out[base + D2 * D2 + D2 + 1] = o[7];
}

__global__ void idwt_l0(const float* __restrict__ approx, const float* __restrict__ det) {
    idwt_cf_body<16>(approx, det, g_vol0);
}
__global__ void idwt_l1(const float* __restrict__ det) {
    idwt_cf_body<32>(g_vol0, det, g_vol1);
}

// Level 2: channel-first fp32 (g_vol1 + details_2, D=64) -> channel-LAST fp16 g_vol2
// with padded channel stride C_PAD.
__global__ void __launch_bounds__(256) idwt_l2(const float* __restrict__ det) {
    __shared__ float sm[8 * C_CH * 33];

    const int j  = blockIdx.x;
    const int i  = blockIdx.y;
    const int k0 = blockIdx.z * 32;
    const int tid = threadIdx.x;

    const int rowbase = i * 64 * 64 + j * 64 + k0;  // within one 64^3 channel plane

    for (int r = tid; r < 8 * C_CH * 32; r += 256) {
        int kk  = r & 31;
        int row = r >> 5;             // s*28 + c
        int s   = row / C_CH;
        int c   = row - s * C_CH;
        const float* src = (s == 0)
            ? (g_vol1 + c * 262144 + rowbase)
            : (det + ((s - 1) * C_CH + c) * 262144 + rowbase);
        sm[row * 33 + kk] = src[kk];
    }
    __syncthreads();

    const int lane = tid & 31;
    const int w    = tid >> 5;          // 8 warps
    const int grp  = lane >> 4;         // 0 or 1 (half-warp)
    const int p    = lane & 15;         // channel-pair index, active if < 14
    if (p < 14) {
        const int c0 = 2 * p;
#pragma unroll
        for (int it = 0; it < 2; it++) {
            int kk = it * 16 + w * 2 + grp;   // 0..31
            float oA[8], oB[8];
            haar8(sm[(0 * C_CH + c0) * 33 + kk], sm[(1 * C_CH + c0) * 33 + kk],
                  sm[(2 * C_CH + c0) * 33 + kk], sm[(3 * C_CH + c0) * 33 + kk],
                  sm[(4 * C_CH + c0) * 33 + kk], sm[(5 * C_CH + c0) * 33 + kk],
                  sm[(6 * C_CH + c0) * 33 + kk], sm[(7 * C_CH + c0) * 33 + kk], oA);
            haar8(sm[(0 * C_CH + c0 + 1) * 33 + kk], sm[(1 * C_CH + c0 + 1) * 33 + kk],
                  sm[(2 * C_CH + c0 + 1) * 33 + kk], sm[(3 * C_CH + c0 + 1) * 33 + kk],
                  sm[(4 * C_CH + c0 + 1) * 33 + kk], sm[(5 * C_CH + c0 + 1) * 33 + kk],
                  sm[(6 * C_CH + c0 + 1) * 33 + kk], sm[(7 * C_CH + c0 + 1) * 33 + kk], oB);

            int X0 = 2 * (k0 + kk);
            // base voxel (2i, 2j, X0), channels (c0, c0+1); half2 index (c0 even)
            int base2 = ((((2 * i) * 128 + (2 * j)) * 128 + X0) * C_PAD + c0) >> 1;
            __half2* v = ((__half2*)g_vol2) + base2;
            const int SP = (128 * 128 * C_PAD) / 2;   // z stride in half2
            const int SQ = (128 * C_PAD) / 2;         // y stride in half2
            const int SR = C_PAD / 2;                 // x stride in half2
            v[0]            = __floats2half2_rn(oA[0], oB[0]);
            v[SR]           = __floats2half2_rn(oA[1], oB[1]);
            v[SQ]           = __floats2half2_rn(oA[2], oB[2]);
            v[SQ + SR]      = __floats2half2_rn(oA[3], oB[3]);
            v[SP]           = __floats2half2_rn(oA[4], oB[4]);
            v[SP + SR]      = __floats2half2_rn(oA[5], oB[5]);
            v[SP + SQ]      = __floats2half2_rn(oA[6], oB[6]);
            v[SP + SQ + SR] = __floats2half2_rn(oA[7], oB[7]);
        }
    }
}

// Trilinear query over channel-last padded fp16 volume. One thread per point, fp32 acc.
__global__ void __launch_bounds__(128) query_k(const float* __restrict__ xyz,
                                               float* __restrict__ out, int N) {
    int n = blockIdx.x * blockDim.x + threadIdx.x;
    if (n >= N) return;

    float x = xyz[3 * n + 0];
    float y = xyz[3 * n + 1];
    float z = xyz[3 * n + 2];

    const float invb = 1.0f / 1.5f;
    const float half127 = 0.5f * 127.0f;
    float px = (x * invb + 1.0f) * half127;
    float py = (y * invb + 1.0f) * half127;
    float pz = (z * invb + 1.0f) * half127;

    float fpx = floorf(px), fpy = floorf(py), fpz = floorf(pz);
    int ix0 = (int)fpx, iy0 = (int)fpy, iz0 = (int)fpz;
    float fx = px - fpx, fy = py - fpy, fz = pz - fpz;

    const __half* __restrict__ vp = (const __half*)g_vol2;

    float acc[C_CH];
#pragma unroll
    for (int c = 0; c < C_CH; c++) acc[c] = 0.0f;

#pragma unroll
    for (int dz = 0; dz < 2; dz++) {
        int iz = iz0 + dz;
        float wz = dz ? fz : (1.0f - fz);
        bool vz = (iz >= 0) & (iz < 128);
        int izc = min(max(iz, 0), 127);
#pragma unroll
        for (int dy = 0; dy < 2; dy++) {
            int iy = iy0 + dy;
            float wy = dy ? fy : (1.0f - fy);
            bool vy = (iy >= 0) & (iy < 128);
            int iyc = min(max(iy, 0), 127);
#pragma unroll
            for (int dx = 0; dx < 2; dx++) {
                int ix = ix0 + dx;
                float wx = dx ? fx : (1.0f - fx);
                bool vx = (ix >= 0) & (ix < 128);
                int ixc = min(max(ix, 0), 127);

                float wgt = wx * wy * wz;
                wgt = (vx & vy & vz) ? wgt : 0.0f;

                // 64B-aligned voxel record: 4x uint4, first 28 halfs used
                const uint4* p = (const uint4*)(vp + ((izc * 128 + iyc) * 128 + ixc) * C_PAD);

                uint4 v0 = p[0];
                uint4 v1 = p[1];
                uint4 v2 = p[2];
                uint4 v3 = p[3];

                float2 a0 = __half22float2(*(const __half2*)&v0.x);
                float2 a1 = __half22float2(*(const __half2*)&v0.y);
                float2 a2 = __half22float2(*(const __half2*)&v0.z);
                float2 a3 = __half22float2(*(const __half2*)&v0.w);
                acc[0]  = fmaf(wgt, a0.x, acc[0]);   acc[1]  = fmaf(wgt, a0.y, acc[1]);
                acc[2]  = fmaf(wgt, a1.x, acc[2]);   acc[3]  = fmaf(wgt, a1.y, acc[3]);
                acc[4]  = fmaf(wgt, a2.x, acc[4]);   acc[5]  = fmaf(wgt, a2.y, acc[5]);
                acc[6]  = fmaf(wgt, a3.x, acc[6]);   acc[7]  = fmaf(wgt, a3.y, acc[7]);

                float2 b0 = __half22float2(*(const __half2*)&v1.x);
                float2 b1 = __half22float2(*(const __half2*)&v1.y);
                float2 b2 = __half22float2(*(const __half2*)&v1.z);
                float2 b3 = __half22float2(*(const __half2*)&v1.w);
                acc[8]  = fmaf(wgt, b0.x, acc[8]);   acc[9]  = fmaf(wgt, b0.y, acc[9]);
                acc[10] = fmaf(wgt, b1.x, acc[10]);  acc[11] = fmaf(wgt, b1.y, acc[11]);
                acc[12] = fmaf(wgt, b2.x, acc[12]);  acc[13] = fmaf(wgt, b2.y, acc[13]);
                acc[14] = fmaf(wgt, b3.x, acc[14]);  acc[15] = fmaf(wgt, b3.y, acc[15]);

                float2 c0 = __half22float2(*(const __half2*)&v2.x);
                float2 c1 = __half22float2(*(const __half2*)&v2.y);
                float2 c2 = __half22float2(*(const __half2*)&v2.z);
                float2 c3 = __half22float2(*(const __half2*)&v2.w);
                acc[16] = fmaf(wgt, c0.x, acc[16]);  acc[17] = fmaf(wgt, c0.y, acc[17]);
                acc[18] = fmaf(wgt, c1.x, acc[18]);  acc[19] = fmaf(wgt, c1.y, acc[19]);
                acc[20] = fmaf(wgt, c2.x, acc[20]);  acc[21] = fmaf(wgt, c2.y, acc[21]);
                acc[22] = fmaf(wgt, c3.x, acc[22]);  acc[23] = fmaf(wgt, c3.y, acc[23]);

                float2 d0 = __half22float2(*(const __half2*)&v3.x);
                float2 d1 = __half22float2(*(const __half2*)&v3.y);
                acc[24] = fmaf(wgt, d0.x, acc[24]);  acc[25] = fmaf(wgt, d0.y, acc[25]);
                acc[26] = fmaf(wgt, d1.x, acc[26]);  acc[27] = fmaf(wgt, d1.y, acc[27]);
            }
        }
    }

    float4* po = (float4*)(out + (long)n * C_CH);
#pragma unroll
    for (int t = 0; t < 7; t++) {
        po[t] = make_float4(acc[4 * t + 0], acc[4 * t + 1], acc[4 * t + 2], acc[4 * t + 3]);
    }
}

extern "C" void kernel_launch(void* const* d_in, const int* in_sizes, int n_in,
                              void* d_out, int out_size) {
    const float* approx    = (const float*)d_in[0];   // (28,16,16,16)
    const float* details_0 = (const float*)d_in[1];   // (7,28,16,16,16)
    const float* details_1 = (const float*)d_in[2];   // (7,28,32,32,32)
    const float* details_2 = (const float*)d_in[3];   // (7,28,64,64,64)
    const float* xyz       = (const float*)d_in[4];   // (N,3)
    float* out = (float*)d_out;

    int N = in_sizes[4] / 3;

    idwt_l0<<<(C_CH * 4096 + 255) / 256, 256>>>(approx, details_0);
    idwt_l1<<<(C_CH * 32768 + 255) / 256, 256>>>(details_1);
    dim3 g2(64, 64, 2);
    idwt_l2<<<g2, 256>>>(details_2);
    query_k<<<(N + 127) / 128, 128>>>(xyz, out, N);
}